// round 12
// baseline (speedup 1.0000x reference)
#include <cuda_runtime.h>
#include <cstdint>
#include <cstddef>

#define NN 50000
#define NE 800000
#define NG 128
#define D  128
#define NL 4
#define NC 10
#define GN_EPS 1e-5f
#define SLOTW 128
#define NT 391                    // ceil(NN/128) M-tiles
#define TILE_FLOATS 16384         // 128x128 fp32
#define GN_CH 16                  // graphnorm stats chunks per graph

// smem layout (floats) for mma_mlp: Ah[128][132] | Al[128][132] | Wh[32][136] | Wl[32][136]
#define PA 132
#define PW 136
#define OFF_AL 16896
#define OFF_WH 33792
#define OFF_WL 38144
#define FMLP_SMEM_FLOATS 42496
#define FMLP_SMEM_BYTES (FMLP_SMEM_FLOATS * 4)

// ---------------- scratch ----------------
__device__ float g_H[NN * D];
__device__ float g_B[NN * D];
__device__ float g_Ahi[(size_t)NT * 128 * D];     // A operand hi, row-major [row][128]
__device__ float g_Alo[(size_t)NT * 128 * D];     // A operand lo
__device__ float g_Wt[16 * TILE_FLOATS];          // per layer: W1hi,W1lo,W2hi,W2lo
__device__ float g_ps[NG * GN_CH * D];            // GN partial sums
__device__ float g_pq[NG * GN_CH * D];            // GN partial sumsq
__device__ float g_An[NG * D];                    // GN precomputed a = mu*ms
__device__ float g_In[NG * D];                    // GN precomputed w*inv
__device__ float g_pool[NG * D];
__device__ float g_f1[NG * D];
__device__ float g_f2[NG * D];
__device__ int   g_off[NG + 1];
__device__ int   g_is64;
__device__ int   g_deg[NN];
__device__ int   g_slots[(size_t)NN * SLOTW];

// ---------------- helpers ----------------
__device__ __forceinline__ uint32_t f2tf32(float x) {
    uint32_t r;
    asm("cvt.rna.tf32.f32 %0, %1;" : "=r"(r) : "f"(x));
    return r;
}
__device__ __forceinline__ void mma8(float* d, const uint32_t* a, uint32_t b0, uint32_t b1) {
    asm volatile(
        "mma.sync.aligned.m16n8k8.row.col.f32.tf32.tf32.f32 "
        "{%0,%1,%2,%3}, {%4,%5,%6,%7}, {%8,%9}, {%0,%1,%2,%3};"
        : "+f"(d[0]), "+f"(d[1]), "+f"(d[2]), "+f"(d[3])
        : "r"(a[0]), "r"(a[1]), "r"(a[2]), "r"(a[3]), "r"(b0), "r"(b1));
}

// ---------------- prep kernels ----------------
__global__ void detect_kernel(const int* __restrict__ p) {
    if (threadIdx.x == 0 && blockIdx.x == 0) {
        int s = 0;
        for (int i = 0; i < 128; i++) s |= p[2 * i + 1];
        g_is64 = (s == 0) ? 1 : 0;
    }
}

__global__ void zerodeg_kernel() {
    int i = blockIdx.x * blockDim.x + threadIdx.x;
    if (i < NN) g_deg[i] = 0;
    if (i < NG * D) g_pool[i] = 0.f;
}

__global__ void offsets_kernel(const void* __restrict__ batch_raw, int n) {
    int i = blockIdx.x * blockDim.x + threadIdx.x;
    if (i >= n) return;
    const int is64 = g_is64;
    const int* b32 = (const int*)batch_raw;
    const long long* b64 = (const long long*)batch_raw;
    int b = is64 ? (int)b64[i] : b32[i];
    if (i == 0) {
        for (int g = 0; g <= b; g++) g_off[g] = 0;
    } else {
        int p = is64 ? (int)b64[i - 1] : b32[i - 1];
        if (b != p) for (int g = p + 1; g <= b; g++) g_off[g] = i;
    }
    if (i == n - 1) {
        for (int g = b + 1; g <= NG; g++) g_off[g] = n;
    }
}

__global__ void fill_kernel(const void* __restrict__ ei_raw) {
    int i = blockIdx.x * blockDim.x + threadIdx.x;
    if (i >= NE) return;
    int s, d;
    if (g_is64) {
        const long long* e = (const long long*)ei_raw;
        s = (int)e[i];
        d = (int)e[NE + i];
    } else {
        const int* e = (const int*)ei_raw;
        s = e[i];
        d = e[NE + i];
    }
    int pos = atomicAdd(&g_deg[d], 1);
    if (pos < SLOTW) g_slots[(size_t)d * SLOTW + pos] = s;
}

// W split: hi/lo tf32 parts, layout kept [k][n] row-major (mma B operand reads B[k][n])
__global__ void wsplit_kernel(const float* __restrict__ gw1, const float* __restrict__ gw2) {
    int idx = blockIdx.x * blockDim.x + threadIdx.x;   // 4*2*16384
    if (idx >= 4 * 2 * TILE_FLOATS) return;
    int l = idx >> 15;
    int m = (idx >> 14) & 1;
    int e = idx & (TILE_FLOATS - 1);
    const float* src = (m ? gw2 : gw1) + (size_t)l * TILE_FLOATS;
    float v = src[e];
    uint32_t hb = f2tf32(v);
    float lo = v - __uint_as_float(hb);
    float* dst = g_Wt + (size_t)(l * 4 + m * 2) * TILE_FLOATS;
    dst[e] = __uint_as_float(hb);
    dst[TILE_FLOATS + e] = __uint_as_float(f2tf32(lo));
}

// ---------------- gather aggregation -> hi/lo split row-major ----------------
__global__ void __launch_bounds__(256) agg_kernel(const float* __restrict__ in) {
    int n = (blockIdx.x * blockDim.x + threadIdx.x) >> 5;
    int lane = threadIdx.x & 31;
    if (n >= NN) return;
    const float4* in4 = (const float4*)in;
    const int* sl = g_slots + (size_t)n * SLOTW;
    int deg = g_deg[n];
    if (deg > SLOTW) deg = SLOTW;

    float4 acc = in4[(size_t)n * 32 + lane];
    int e = 0;
    for (; e + 4 <= deg; e += 4) {
        int s0 = sl[e], s1 = sl[e + 1], s2 = sl[e + 2], s3 = sl[e + 3];
        float4 v0 = in4[(size_t)s0 * 32 + lane];
        float4 v1 = in4[(size_t)s1 * 32 + lane];
        float4 v2 = in4[(size_t)s2 * 32 + lane];
        float4 v3 = in4[(size_t)s3 * 32 + lane];
        acc.x += v0.x + v1.x + v2.x + v3.x;
        acc.y += v0.y + v1.y + v2.y + v3.y;
        acc.z += v0.z + v1.z + v2.z + v3.z;
        acc.w += v0.w + v1.w + v2.w + v3.w;
    }
    for (; e < deg; e++) {
        int s0 = sl[e];
        float4 v0 = in4[(size_t)s0 * 32 + lane];
        acc.x += v0.x; acc.y += v0.y; acc.z += v0.z; acc.w += v0.w;
    }
    float v[4] = {acc.x, acc.y, acc.z, acc.w};
    float4 hi4, lo4;
    float* hp = (float*)&hi4;
    float* lp = (float*)&lo4;
#pragma unroll
    for (int j = 0; j < 4; j++) {
        uint32_t hb = f2tf32(v[j]);
        float lo = v[j] - __uint_as_float(hb);
        hp[j] = __uint_as_float(hb);
        lp[j] = __uint_as_float(f2tf32(lo));
    }
    *(float4*)(g_Ahi + (size_t)n * 128 + lane * 4) = hi4;
    *(float4*)(g_Alo + (size_t)n * 128 + lane * 4) = lo4;
}

// ---------------- fused MLP on tensor cores (mma.sync tf32, 3x compensated) ----------------
// C = relu(relu(A@W1+b1)@W2+b2). 256 threads = 8 warps (4 M x 2 N), warp tile 32x64.
__global__ void __launch_bounds__(256, 1) mma_mlp_kernel(
    const float* __restrict__ Ahi, const float* __restrict__ Alo,
    const float* __restrict__ Wbase,   // W1hi | W1lo | W2hi | W2lo, each 16384 floats
    const float* __restrict__ b1, const float* __restrict__ b2,
    float* __restrict__ C, int M)
{
    extern __shared__ float sm[];
    float* Ah = sm;
    float* Al = sm + OFF_AL;
    float* Wh = sm + OFF_WH;
    float* Wl = sm + OFF_WL;

    int tid = threadIdx.x;
    int w = tid >> 5;
    int lane = tid & 31;
    int wm = w & 3;
    int wn = w >> 2;
    int q = lane >> 2;              // 0..7
    int r = lane & 3;               // 0..3
    int m0 = blockIdx.x * 128;

    // load A slice (hi/lo) into padded smem
    {
        const float4* sh = (const float4*)(Ahi + (size_t)m0 * 128);
        const float4* slo = (const float4*)(Alo + (size_t)m0 * 128);
#pragma unroll
        for (int t = 0; t < 16; t++) {
            int i = t * 256 + tid;
            int row = i >> 5;
            int c4 = (i & 31) * 4;
            *(float4*)&Ah[row * PA + c4] = sh[i];
            *(float4*)&Al[row * PA + c4] = slo[i];
        }
    }

    float dacc[2][8][4];

    for (int ph = 0; ph < 2; ph++) {
        const float* WHsrc = Wbase + (ph ? 2 : 0) * TILE_FLOATS;
        const float* WLsrc = WHsrc + TILE_FLOATS;
#pragma unroll
        for (int mt = 0; mt < 2; mt++)
#pragma unroll
            for (int nt = 0; nt < 8; nt++)
#pragma unroll
                for (int j = 0; j < 4; j++) dacc[mt][nt][j] = 0.f;

        for (int chunk = 0; chunk < 4; chunk++) {
            __syncthreads();   // prev chunk compute done / A copy or epilogue-1 visible
#pragma unroll
            for (int t = 0; t < 4; t++) {
                int i = t * 256 + tid;       // 1024 float4 = 32 rows x 32
                int row = i >> 5;
                int c4 = (i & 31) * 4;
                *(float4*)&Wh[row * PW + c4] =
                    *(const float4*)&WHsrc[(size_t)(chunk * 32 + row) * 128 + c4];
                *(float4*)&Wl[row * PW + c4] =
                    *(const float4*)&WLsrc[(size_t)(chunk * 32 + row) * 128 + c4];
            }
            __syncthreads();

#pragma unroll
            for (int ks = 0; ks < 4; ks++) {
                int k0 = chunk * 32 + ks * 8;   // A column base
                int kl = ks * 8;                // W chunk row base
                uint32_t ah[2][4], al[2][4];
#pragma unroll
                for (int mt = 0; mt < 2; mt++) {
                    int rb = wm * 32 + mt * 16 + q;
                    ah[mt][0] = __float_as_uint(Ah[rb * PA + k0 + r]);
                    ah[mt][1] = __float_as_uint(Ah[(rb + 8) * PA + k0 + r]);
                    ah[mt][2] = __float_as_uint(Ah[rb * PA + k0 + r + 4]);
                    ah[mt][3] = __float_as_uint(Ah[(rb + 8) * PA + k0 + r + 4]);
                    al[mt][0] = __float_as_uint(Al[rb * PA + k0 + r]);
                    al[mt][1] = __float_as_uint(Al[(rb + 8) * PA + k0 + r]);
                    al[mt][2] = __float_as_uint(Al[rb * PA + k0 + r + 4]);
                    al[mt][3] = __float_as_uint(Al[(rb + 8) * PA + k0 + r + 4]);
                }
#pragma unroll
                for (int nt = 0; nt < 8; nt++) {
                    int nb = wn * 64 + nt * 8 + q;
                    uint32_t bh0 = __float_as_uint(Wh[(kl + r) * PW + nb]);
                    uint32_t bh1 = __float_as_uint(Wh[(kl + r + 4) * PW + nb]);
                    uint32_t bl0 = __float_as_uint(Wl[(kl + r) * PW + nb]);
                    uint32_t bl1 = __float_as_uint(Wl[(kl + r + 4) * PW + nb]);
#pragma unroll
                    for (int mt = 0; mt < 2; mt++) {
                        mma8(dacc[mt][nt], ah[mt], bh0, bh1);
                        mma8(dacc[mt][nt], al[mt], bh0, bh1);
                        mma8(dacc[mt][nt], ah[mt], bl0, bl1);
                    }
                }
            }
        }
        __syncthreads();   // all warps done reading Ah/Al for this phase

        if (ph == 0) {
            // epilogue 1: z = relu(d + b1), split hi/lo back into Ah/Al
#pragma unroll
            for (int mt = 0; mt < 2; mt++) {
#pragma unroll
                for (int nt = 0; nt < 8; nt++) {
                    int c0 = wn * 64 + nt * 8 + r * 2;
                    int rw0 = wm * 32 + mt * 16 + q;
                    float bb0 = __ldg(b1 + c0);
                    float bb1 = __ldg(b1 + c0 + 1);
                    float z[4];
                    z[0] = fmaxf(dacc[mt][nt][0] + bb0, 0.f);
                    z[1] = fmaxf(dacc[mt][nt][1] + bb1, 0.f);
                    z[2] = fmaxf(dacc[mt][nt][2] + bb0, 0.f);
                    z[3] = fmaxf(dacc[mt][nt][3] + bb1, 0.f);
                    int rows[4] = {rw0, rw0, rw0 + 8, rw0 + 8};
                    int cols[4] = {c0, c0 + 1, c0, c0 + 1};
#pragma unroll
                    for (int j = 0; j < 4; j++) {
                        uint32_t hb = f2tf32(z[j]);
                        float lo = z[j] - __uint_as_float(hb);
                        Ah[rows[j] * PA + cols[j]] = __uint_as_float(hb);
                        Al[rows[j] * PA + cols[j]] = __uint_as_float(f2tf32(lo));
                    }
                }
            }
        } else {
            // epilogue 2: C = relu(d + b2)
#pragma unroll
            for (int mt = 0; mt < 2; mt++) {
                int rw0 = m0 + wm * 32 + mt * 16 + q;
#pragma unroll
                for (int nt = 0; nt < 8; nt++) {
                    int c0 = wn * 64 + nt * 8 + r * 2;
                    float bb0 = __ldg(b2 + c0);
                    float bb1 = __ldg(b2 + c0 + 1);
                    if (rw0 < M) {
                        float2 o;
                        o.x = fmaxf(dacc[mt][nt][0] + bb0, 0.f);
                        o.y = fmaxf(dacc[mt][nt][1] + bb1, 0.f);
                        *(float2*)(C + (size_t)rw0 * 128 + c0) = o;
                    }
                    if (rw0 + 8 < M) {
                        float2 o;
                        o.x = fmaxf(dacc[mt][nt][2] + bb0, 0.f);
                        o.y = fmaxf(dacc[mt][nt][3] + bb1, 0.f);
                        *(float2*)(C + (size_t)(rw0 + 8) * 128 + c0) = o;
                    }
                }
            }
        }
    }
}

// ---------------- GraphNorm split: stats -> reduce -> apply ----------------
// stats: grid (NG, GN_CH), 128 threads; partial sum/sumsq per chunk, no races
__global__ void __launch_bounds__(128) gn_stats_kernel(const float* __restrict__ in) {
    int g = blockIdx.x;
    int ch = blockIdx.y;
    int d = threadIdx.x;
    int n0 = g_off[g];
    int n1 = g_off[g + 1];
    float s = 0.f, qq = 0.f;
    for (int i = n0 + ch; i < n1; i += GN_CH) {
        float v = __ldg(in + (size_t)i * D + d);
        s += v;
        qq += v * v;
    }
    g_ps[(g * GN_CH + ch) * D + d] = s;
    g_pq[(g * GN_CH + ch) * D + d] = qq;
}

// reduce: grid NG, 128 threads; fold partials, precompute A = mu*ms and I = w*rsqrt(var+eps)
__global__ void __launch_bounds__(128) gn_reduce_kernel(
    const float* __restrict__ w, const float* __restrict__ ms)
{
    int g = blockIdx.x;
    int d = threadIdx.x;
    int n0 = g_off[g];
    int n1 = g_off[g + 1];
    float cnt = (float)((n1 - n0) > 0 ? (n1 - n0) : 1);
    float S = 0.f, Q = 0.f;
#pragma unroll
    for (int c = 0; c < GN_CH; c++) {
        S += g_ps[(g * GN_CH + c) * D + d];
        Q += g_pq[(g * GN_CH + c) * D + d];
    }
    float mu = S / cnt;
    float a = mu * ms[d];
    float var = Q / cnt - 2.f * a * mu + a * a;
    g_An[g * D + d] = a;
    g_In[g * D + d] = w[d] * rsqrtf(var + GN_EPS);
}

// apply: grid ceil(NN/64), 128 threads; o = relu(I*(v-A) + bias); last layer pools via atomics
__global__ void __launch_bounds__(128) gn_apply_kernel(
    const float* __restrict__ in, float* __restrict__ outp,
    const float* __restrict__ bi, const void* __restrict__ batch_raw, int last)
{
    int d = threadIdx.x;
    int r0 = blockIdx.x * 64;
    int r1 = r0 + 64;
    if (r1 > NN) r1 = NN;
    const int is64 = g_is64;
    const int* b32 = (const int*)batch_raw;
    const long long* b64 = (const long long*)batch_raw;
    float bd = bi[d];
    int cur_g = -1;
    float A = 0.f, I = 0.f, ps = 0.f;
    for (int i = r0; i < r1; i++) {
        int g = is64 ? (int)b64[i] : b32[i];
        if (g != cur_g) {
            if (last && cur_g >= 0) atomicAdd(&g_pool[cur_g * D + d], ps);
            ps = 0.f;
            cur_g = g;
            A = g_An[g * D + d];
            I = g_In[g * D + d];
        }
        size_t idx = (size_t)i * D + d;
        float o = fmaxf(I * (__ldg(in + idx) - A) + bd, 0.f);
        outp[idx] = o;
        ps += o;
    }
    if (last && cur_g >= 0) atomicAdd(&g_pool[cur_g * D + d], ps);
}

// ---------------- small FC ----------------
__global__ void __launch_bounds__(128) fc_kernel(
    const float* __restrict__ in, const float* __restrict__ W,
    const float* __restrict__ bias, float* __restrict__ out, int do_relu)
{
    __shared__ float s[128];
    int g = blockIdx.x;
    int j = threadIdx.x;
    s[j] = in[g * 128 + j];
    __syncthreads();
    float acc = bias[j];
#pragma unroll 8
    for (int k = 0; k < 128; k++) acc += s[k] * W[k * 128 + j];
    out[g * 128 + j] = do_relu ? fmaxf(acc, 0.f) : acc;
}

// ---------------- logits + log_softmax ----------------
__global__ void __launch_bounds__(32) logits_kernel(
    const float* __restrict__ fw3, const float* __restrict__ fb3,
    float* __restrict__ out)
{
    __shared__ float s[128];
    __shared__ float lg[NC];
    __shared__ float lse;
    int g = blockIdx.x;
    int t = threadIdx.x;
    for (int k = t; k < 128; k += 32) s[k] = g_f2[g * 128 + k];
    __syncthreads();
    if (t < NC) {
        float acc = fb3[t];
#pragma unroll 8
        for (int k = 0; k < 128; k++) acc += s[k] * fw3[k * NC + t];
        lg[t] = acc;
    }
    __syncthreads();
    if (t == 0) {
        float mx = lg[0];
        for (int c = 1; c < NC; c++) mx = fmaxf(mx, lg[c]);
        float se = 0.f;
        for (int c = 0; c < NC; c++) se += expf(lg[c] - mx);
        lse = mx + logf(se);
    }
    __syncthreads();
    if (t < NC) out[g * NC + t] = lg[t] - lse;
}

// ---------------- launch ----------------
extern "C" void kernel_launch(void* const* d_in, const int* in_sizes, int n_in,
                              void* d_out, int out_size)
{
    const float* x       = (const float*)d_in[0];
    const float* gw1     = (const float*)d_in[1];
    const float* gb1     = (const float*)d_in[2];
    const float* gw2     = (const float*)d_in[3];
    const float* gb2     = (const float*)d_in[4];
    const float* gnw     = (const float*)d_in[5];
    const float* gnb     = (const float*)d_in[6];
    const float* gns     = (const float*)d_in[7];
    const float* fw1     = (const float*)d_in[8];
    const float* fb1     = (const float*)d_in[9];
    const float* fw2     = (const float*)d_in[10];
    const float* fb2     = (const float*)d_in[11];
    const float* fw3     = (const float*)d_in[12];
    const float* fb3     = (const float*)d_in[13];
    const void*  ei      = d_in[14];
    const void*  batch   = d_in[15];
    float* out = (float*)d_out;

    float *Hp, *Bp, *Ahip, *Alop, *Wtp, *poolp, *f1p, *f2p;
    cudaGetSymbolAddress((void**)&Hp, g_H);
    cudaGetSymbolAddress((void**)&Bp, g_B);
    cudaGetSymbolAddress((void**)&Ahip, g_Ahi);
    cudaGetSymbolAddress((void**)&Alop, g_Alo);
    cudaGetSymbolAddress((void**)&Wtp, g_Wt);
    cudaGetSymbolAddress((void**)&poolp, g_pool);
    cudaGetSymbolAddress((void**)&f1p, g_f1);
    cudaGetSymbolAddress((void**)&f2p, g_f2);

    cudaFuncSetAttribute(mma_mlp_kernel,
                         cudaFuncAttributeMaxDynamicSharedMemorySize,
                         FMLP_SMEM_BYTES);

    detect_kernel<<<1, 32>>>((const int*)ei);
    zerodeg_kernel<<<(NN + 255) / 256, 256>>>();
    offsets_kernel<<<(NN + 255) / 256, 256>>>(batch, NN);
    fill_kernel<<<(NE + 255) / 256, 256>>>(ei);
    wsplit_kernel<<<(4 * 2 * TILE_FLOATS + 255) / 256, 256>>>(gw1, gw2);

    const int agg_blocks = (NN * 32 + 255) / 256;
    const int apply_blocks = (NN + 63) / 64;

    for (int l = 0; l < NL; l++) {
        const float* hin = (l == 0) ? x : Hp;
        agg_kernel<<<agg_blocks, 256>>>(hin);
        mma_mlp_kernel<<<NT, 256, FMLP_SMEM_BYTES>>>(
            Ahip, Alop, Wtp + (size_t)l * 4 * TILE_FLOATS,
            gb1 + l * D, gb2 + l * D, Bp, NN);
        gn_stats_kernel<<<dim3(NG, GN_CH), 128>>>(Bp);
        gn_reduce_kernel<<<NG, 128>>>(gnw + l * D, gns + l * D);
        gn_apply_kernel<<<apply_blocks, 128>>>(Bp, Hp, gnb + l * D, batch,
                                               (l == NL - 1) ? 1 : 0);
    }

    fc_kernel<<<NG, 128>>>(poolp, fw1, fb1, f1p, 1);
    fc_kernel<<<NG, 128>>>(f1p, fw2, fb2, f2p, 1);
    logits_kernel<<<NG, 32>>>(fw3, fb3, out);
}

// round 13
// speedup vs baseline: 1.1570x; 1.1570x over previous
#include <cuda_runtime.h>
#include <cstdint>
#include <cstddef>

#define NN 50000
#define NE 800000
#define NG 128
#define D  128
#define NL 4
#define NC 10
#define GN_EPS 1e-5f
#define SLOTW 128
#define NT 391                    // ceil(NN/128) M-tiles
#define TILE_FLOATS 16384         // 128x128 fp32

// smem layout (floats) for mma_mlp: As[128][132] fp32 | Wh[32][136] | Wl[32][136]
#define PA 132
#define PW 136
#define OFF_WH 16896
#define OFF_WL 21248
#define FMLP_SMEM_FLOATS 25600
#define FMLP_SMEM_BYTES (FMLP_SMEM_FLOATS * 4)   // 102400 -> 2 CTAs/SM

// ---------------- scratch ----------------
__device__ float g_H[NN * D];
__device__ float g_B[NN * D];
__device__ float g_A[(size_t)NT * 128 * D];       // aggregation output fp32 (tail rows stay 0)
__device__ float g_Wt[16 * TILE_FLOATS];          // per layer: W1hi,W1lo,W2hi,W2lo
__device__ float g_pool[NG * D];
__device__ float g_f1[NG * D];
__device__ float g_f2[NG * D];
__device__ int   g_off[NG + 1];
__device__ int   g_is64;
__device__ int   g_deg[NN];
__device__ int   g_slots[(size_t)NN * SLOTW];

// ---------------- helpers ----------------
__device__ __forceinline__ uint32_t f2tf32(float x) {
    uint32_t r;
    asm("cvt.rna.tf32.f32 %0, %1;" : "=r"(r) : "f"(x));
    return r;
}
__device__ __forceinline__ void mma8(float* d, const uint32_t* a, uint32_t b0, uint32_t b1) {
    asm volatile(
        "mma.sync.aligned.m16n8k8.row.col.f32.tf32.tf32.f32 "
        "{%0,%1,%2,%3}, {%4,%5,%6,%7}, {%8,%9}, {%0,%1,%2,%3};"
        : "+f"(d[0]), "+f"(d[1]), "+f"(d[2]), "+f"(d[3])
        : "r"(a[0]), "r"(a[1]), "r"(a[2]), "r"(a[3]), "r"(b0), "r"(b1));
}

// ---------------- prep kernels ----------------
__global__ void detect_kernel(const int* __restrict__ p) {
    if (threadIdx.x == 0 && blockIdx.x == 0) {
        int s = 0;
        for (int i = 0; i < 128; i++) s |= p[2 * i + 1];
        g_is64 = (s == 0) ? 1 : 0;
    }
}

__global__ void zerodeg_kernel() {
    int i = blockIdx.x * blockDim.x + threadIdx.x;
    if (i < NN) g_deg[i] = 0;
}

__global__ void offsets_kernel(const void* __restrict__ batch_raw, int n) {
    int i = blockIdx.x * blockDim.x + threadIdx.x;
    if (i >= n) return;
    const int is64 = g_is64;
    const int* b32 = (const int*)batch_raw;
    const long long* b64 = (const long long*)batch_raw;
    int b = is64 ? (int)b64[i] : b32[i];
    if (i == 0) {
        for (int g = 0; g <= b; g++) g_off[g] = 0;
    } else {
        int p = is64 ? (int)b64[i - 1] : b32[i - 1];
        if (b != p) for (int g = p + 1; g <= b; g++) g_off[g] = i;
    }
    if (i == n - 1) {
        for (int g = b + 1; g <= NG; g++) g_off[g] = n;
    }
}

__global__ void fill_kernel(const void* __restrict__ ei_raw) {
    int i = blockIdx.x * blockDim.x + threadIdx.x;
    if (i >= NE) return;
    int s, d;
    if (g_is64) {
        const long long* e = (const long long*)ei_raw;
        s = (int)e[i];
        d = (int)e[NE + i];
    } else {
        const int* e = (const int*)ei_raw;
        s = e[i];
        d = e[NE + i];
    }
    int pos = atomicAdd(&g_deg[d], 1);
    if (pos < SLOTW) g_slots[(size_t)d * SLOTW + pos] = s;
}

// W split: hi/lo tf32 parts, layout kept [k][n] row-major (mma B operand reads B[k][n])
__global__ void wsplit_kernel(const float* __restrict__ gw1, const float* __restrict__ gw2) {
    int idx = blockIdx.x * blockDim.x + threadIdx.x;   // 4*2*16384
    if (idx >= 4 * 2 * TILE_FLOATS) return;
    int l = idx >> 15;
    int m = (idx >> 14) & 1;
    int e = idx & (TILE_FLOATS - 1);
    const float* src = (m ? gw2 : gw1) + (size_t)l * TILE_FLOATS;
    float v = src[e];
    uint32_t hb = f2tf32(v);
    float lo = v - __uint_as_float(hb);
    float* dst = g_Wt + (size_t)(l * 4 + m * 2) * TILE_FLOATS;
    dst[e] = __uint_as_float(hb);
    dst[TILE_FLOATS + e] = __uint_as_float(f2tf32(lo));
}

// ---------------- gather aggregation -> fp32 row-major ----------------
__global__ void __launch_bounds__(256) agg_kernel(const float* __restrict__ in) {
    int n = (blockIdx.x * blockDim.x + threadIdx.x) >> 5;
    int lane = threadIdx.x & 31;
    if (n >= NN) return;
    const float4* in4 = (const float4*)in;
    const int* sl = g_slots + (size_t)n * SLOTW;
    int deg = g_deg[n];
    if (deg > SLOTW) deg = SLOTW;

    float4 acc = in4[(size_t)n * 32 + lane];
    int e = 0;
    for (; e + 4 <= deg; e += 4) {
        int s0 = sl[e], s1 = sl[e + 1], s2 = sl[e + 2], s3 = sl[e + 3];
        float4 v0 = in4[(size_t)s0 * 32 + lane];
        float4 v1 = in4[(size_t)s1 * 32 + lane];
        float4 v2 = in4[(size_t)s2 * 32 + lane];
        float4 v3 = in4[(size_t)s3 * 32 + lane];
        acc.x += v0.x + v1.x + v2.x + v3.x;
        acc.y += v0.y + v1.y + v2.y + v3.y;
        acc.z += v0.z + v1.z + v2.z + v3.z;
        acc.w += v0.w + v1.w + v2.w + v3.w;
    }
    for (; e < deg; e++) {
        int s0 = sl[e];
        float4 v0 = in4[(size_t)s0 * 32 + lane];
        acc.x += v0.x; acc.y += v0.y; acc.z += v0.z; acc.w += v0.w;
    }
    *(float4*)(g_A + (size_t)n * 128 + lane * 4) = acc;
}

// ---------------- fused MLP on tensor cores (mma.sync tf32, 3x compensated) ----------------
// C = relu(relu(A@W1+b1)@W2+b2). 256 threads = 8 warps (4 M x 2 N), warp tile 32x64.
// A tile lives in smem as fp32; tf32 hi/lo derived in registers at fragment load.
__global__ void __launch_bounds__(256, 2) mma_mlp_kernel(
    const float* __restrict__ A,
    const float* __restrict__ Wbase,   // W1hi | W1lo | W2hi | W2lo, each 16384 floats
    const float* __restrict__ b1, const float* __restrict__ b2,
    float* __restrict__ C, int M)
{
    extern __shared__ float sm[];
    float* As = sm;                 // [128][PA] fp32
    float* Wh = sm + OFF_WH;
    float* Wl = sm + OFF_WL;

    int tid = threadIdx.x;
    int w = tid >> 5;
    int lane = tid & 31;
    int wm = w & 3;
    int wn = w >> 2;
    int q = lane >> 2;              // 0..7
    int r = lane & 3;               // 0..3
    int m0 = blockIdx.x * 128;

    // load A slice (fp32) into padded smem
    {
        const float4* sa = (const float4*)(A + (size_t)m0 * 128);
#pragma unroll
        for (int t = 0; t < 16; t++) {
            int i = t * 256 + tid;          // 4096 float4
            int row = i >> 5;
            int c4 = (i & 31) * 4;
            *(float4*)&As[row * PA + c4] = sa[i];
        }
    }

    float dacc[2][8][4];

    for (int ph = 0; ph < 2; ph++) {
        const float* WHsrc = Wbase + (ph ? 2 : 0) * TILE_FLOATS;
        const float* WLsrc = WHsrc + TILE_FLOATS;
#pragma unroll
        for (int mt = 0; mt < 2; mt++)
#pragma unroll
            for (int nt = 0; nt < 8; nt++)
#pragma unroll
                for (int j = 0; j < 4; j++) dacc[mt][nt][j] = 0.f;

        for (int chunk = 0; chunk < 4; chunk++) {
            __syncthreads();   // prev chunk compute done / A copy or epilogue-1 visible
#pragma unroll
            for (int t = 0; t < 4; t++) {
                int i = t * 256 + tid;       // 1024 float4 = 32 rows x 32
                int row = i >> 5;
                int c4 = (i & 31) * 4;
                *(float4*)&Wh[row * PW + c4] =
                    *(const float4*)&WHsrc[(size_t)(chunk * 32 + row) * 128 + c4];
                *(float4*)&Wl[row * PW + c4] =
                    *(const float4*)&WLsrc[(size_t)(chunk * 32 + row) * 128 + c4];
            }
            __syncthreads();

#pragma unroll
            for (int ks = 0; ks < 4; ks++) {
                int k0 = chunk * 32 + ks * 8;   // A column base
                int kl = ks * 8;                // W chunk row base
                uint32_t ah[2][4], al[2][4];
#pragma unroll
                for (int mt = 0; mt < 2; mt++) {
                    int rb = wm * 32 + mt * 16 + q;
                    float v0 = As[rb * PA + k0 + r];
                    float v1 = As[(rb + 8) * PA + k0 + r];
                    float v2 = As[rb * PA + k0 + r + 4];
                    float v3 = As[(rb + 8) * PA + k0 + r + 4];
                    ah[mt][0] = f2tf32(v0);
                    ah[mt][1] = f2tf32(v1);
                    ah[mt][2] = f2tf32(v2);
                    ah[mt][3] = f2tf32(v3);
                    al[mt][0] = f2tf32(v0 - __uint_as_float(ah[mt][0]));
                    al[mt][1] = f2tf32(v1 - __uint_as_float(ah[mt][1]));
                    al[mt][2] = f2tf32(v2 - __uint_as_float(ah[mt][2]));
                    al[mt][3] = f2tf32(v3 - __uint_as_float(ah[mt][3]));
                }
#pragma unroll
                for (int nt = 0; nt < 8; nt++) {
                    int nb = wn * 64 + nt * 8 + q;
                    uint32_t bh0 = __float_as_uint(Wh[(kl + r) * PW + nb]);
                    uint32_t bh1 = __float_as_uint(Wh[(kl + r + 4) * PW + nb]);
                    uint32_t bl0 = __float_as_uint(Wl[(kl + r) * PW + nb]);
                    uint32_t bl1 = __float_as_uint(Wl[(kl + r + 4) * PW + nb]);
#pragma unroll
                    for (int mt = 0; mt < 2; mt++) {
                        mma8(dacc[mt][nt], ah[mt], bh0, bh1);
                        mma8(dacc[mt][nt], al[mt], bh0, bh1);
                        mma8(dacc[mt][nt], ah[mt], bl0, bl1);
                    }
                }
            }
        }
        __syncthreads();   // all warps done reading As for this phase

        if (ph == 0) {
            // epilogue 1: z = relu(d + b1) stored fp32 back into As
#pragma unroll
            for (int mt = 0; mt < 2; mt++) {
#pragma unroll
                for (int nt = 0; nt < 8; nt++) {
                    int c0 = wn * 64 + nt * 8 + r * 2;
                    int rw0 = wm * 32 + mt * 16 + q;
                    float bb0 = __ldg(b1 + c0);
                    float bb1 = __ldg(b1 + c0 + 1);
                    As[rw0 * PA + c0]           = fmaxf(dacc[mt][nt][0] + bb0, 0.f);
                    As[rw0 * PA + c0 + 1]       = fmaxf(dacc[mt][nt][1] + bb1, 0.f);
                    As[(rw0 + 8) * PA + c0]     = fmaxf(dacc[mt][nt][2] + bb0, 0.f);
                    As[(rw0 + 8) * PA + c0 + 1] = fmaxf(dacc[mt][nt][3] + bb1, 0.f);
                }
            }
        } else {
            // epilogue 2: C = relu(d + b2)
#pragma unroll
            for (int mt = 0; mt < 2; mt++) {
                int rw0 = m0 + wm * 32 + mt * 16 + q;
#pragma unroll
                for (int nt = 0; nt < 8; nt++) {
                    int c0 = wn * 64 + nt * 8 + r * 2;
                    float bb0 = __ldg(b2 + c0);
                    float bb1 = __ldg(b2 + c0 + 1);
                    if (rw0 < M) {
                        float2 o;
                        o.x = fmaxf(dacc[mt][nt][0] + bb0, 0.f);
                        o.y = fmaxf(dacc[mt][nt][1] + bb1, 0.f);
                        *(float2*)(C + (size_t)rw0 * 128 + c0) = o;
                    }
                    if (rw0 + 8 < M) {
                        float2 o;
                        o.x = fmaxf(dacc[mt][nt][2] + bb0, 0.f);
                        o.y = fmaxf(dacc[mt][nt][3] + bb1, 0.f);
                        *(float2*)(C + (size_t)(rw0 + 8) * 128 + c0) = o;
                    }
                }
            }
        }
    }
}

// ---------------- GraphNorm + ReLU, 2-pass (sum/sumsq stats) ----------------
__global__ void __launch_bounds__(512) graphnorm_kernel(
    const float* __restrict__ in, float* __restrict__ outp,
    const float* __restrict__ w, const float* __restrict__ bi,
    const float* __restrict__ ms, int last)
{
    __shared__ float rs[4][128];
    __shared__ float rq[4][128];
    int g = blockIdx.x;
    int d = threadIdx.x & 127;
    int ty = threadIdx.x >> 7;
    int n0 = g_off[g];
    int n1 = g_off[g + 1];
    float cnt = (float)((n1 - n0) > 0 ? (n1 - n0) : 1);

    float s = 0.f, qq = 0.f;
    for (int i = n0 + ty; i < n1; i += 4) {
        float v = __ldg(in + (size_t)i * D + d);
        s += v;
        qq += v * v;
    }
    rs[ty][d] = s;
    rq[ty][d] = qq;
    __syncthreads();
    float S = rs[0][d] + rs[1][d] + rs[2][d] + rs[3][d];
    float Q = rq[0][d] + rq[1][d] + rq[2][d] + rq[3][d];
    float mu = S / cnt;
    float a = mu * ms[d];
    float var = Q / cnt - 2.f * a * mu + a * a;
    float inv = rsqrtf(var + GN_EPS);
    float wd = w[d], bd = bi[d];

    float ps = 0.f;
    for (int i = n0 + ty; i < n1; i += 4) {
        size_t idx = (size_t)i * D + d;
        float t = __ldg(in + idx) - a;
        float o = fmaxf(wd * t * inv + bd, 0.f);
        outp[idx] = o;
        ps += o;
    }
    if (last) {
        __syncthreads();
        rs[ty][d] = ps;
        __syncthreads();
        if (ty == 0) g_pool[g * D + d] = rs[0][d] + rs[1][d] + rs[2][d] + rs[3][d];
    }
}

// ---------------- small FC ----------------
__global__ void __launch_bounds__(128) fc_kernel(
    const float* __restrict__ in, const float* __restrict__ W,
    const float* __restrict__ bias, float* __restrict__ out, int do_relu)
{
    __shared__ float s[128];
    int g = blockIdx.x;
    int j = threadIdx.x;
    s[j] = in[g * 128 + j];
    __syncthreads();
    float acc = bias[j];
#pragma unroll 8
    for (int k = 0; k < 128; k++) acc += s[k] * W[k * 128 + j];
    out[g * 128 + j] = do_relu ? fmaxf(acc, 0.f) : acc;
}

// ---------------- logits + log_softmax ----------------
__global__ void __launch_bounds__(32) logits_kernel(
    const float* __restrict__ fw3, const float* __restrict__ fb3,
    float* __restrict__ out)
{
    __shared__ float s[128];
    __shared__ float lg[NC];
    __shared__ float lse;
    int g = blockIdx.x;
    int t = threadIdx.x;
    for (int k = t; k < 128; k += 32) s[k] = g_f2[g * 128 + k];
    __syncthreads();
    if (t < NC) {
        float acc = fb3[t];
#pragma unroll 8
        for (int k = 0; k < 128; k++) acc += s[k] * fw3[k * NC + t];
        lg[t] = acc;
    }
    __syncthreads();
    if (t == 0) {
        float mx = lg[0];
        for (int c = 1; c < NC; c++) mx = fmaxf(mx, lg[c]);
        float se = 0.f;
        for (int c = 0; c < NC; c++) se += expf(lg[c] - mx);
        lse = mx + logf(se);
    }
    __syncthreads();
    if (t < NC) out[g * NC + t] = lg[t] - lse;
}

// ---------------- launch ----------------
extern "C" void kernel_launch(void* const* d_in, const int* in_sizes, int n_in,
                              void* d_out, int out_size)
{
    const float* x       = (const float*)d_in[0];
    const float* gw1     = (const float*)d_in[1];
    const float* gb1     = (const float*)d_in[2];
    const float* gw2     = (const float*)d_in[3];
    const float* gb2     = (const float*)d_in[4];
    const float* gnw     = (const float*)d_in[5];
    const float* gnb     = (const float*)d_in[6];
    const float* gns     = (const float*)d_in[7];
    const float* fw1     = (const float*)d_in[8];
    const float* fb1     = (const float*)d_in[9];
    const float* fw2     = (const float*)d_in[10];
    const float* fb2     = (const float*)d_in[11];
    const float* fw3     = (const float*)d_in[12];
    const float* fb3     = (const float*)d_in[13];
    const void*  ei      = d_in[14];
    const void*  batch   = d_in[15];
    float* out = (float*)d_out;

    float *Hp, *Bp, *Ap, *Wtp, *poolp, *f1p, *f2p;
    cudaGetSymbolAddress((void**)&Hp, g_H);
    cudaGetSymbolAddress((void**)&Bp, g_B);
    cudaGetSymbolAddress((void**)&Ap, g_A);
    cudaGetSymbolAddress((void**)&Wtp, g_Wt);
    cudaGetSymbolAddress((void**)&poolp, g_pool);
    cudaGetSymbolAddress((void**)&f1p, g_f1);
    cudaGetSymbolAddress((void**)&f2p, g_f2);

    cudaFuncSetAttribute(mma_mlp_kernel,
                         cudaFuncAttributeMaxDynamicSharedMemorySize,
                         FMLP_SMEM_BYTES);

    detect_kernel<<<1, 32>>>((const int*)ei);
    zerodeg_kernel<<<(NN + 255) / 256, 256>>>();
    offsets_kernel<<<(NN + 255) / 256, 256>>>(batch, NN);
    fill_kernel<<<(NE + 255) / 256, 256>>>(ei);
    wsplit_kernel<<<(4 * 2 * TILE_FLOATS + 255) / 256, 256>>>(gw1, gw2);

    const int agg_blocks = (NN * 32 + 255) / 256;

    for (int l = 0; l < NL; l++) {
        const float* hin = (l == 0) ? x : Hp;
        agg_kernel<<<agg_blocks, 256>>>(hin);
        mma_mlp_kernel<<<NT, 256, FMLP_SMEM_BYTES>>>(
            Ap, Wtp + (size_t)l * 4 * TILE_FLOATS,
            gb1 + l * D, gb2 + l * D, Bp, NN);
        graphnorm_kernel<<<NG, 512>>>(Bp, Hp,
            gnw + l * D, gnb + l * D, gns + l * D, (l == NL - 1) ? 1 : 0);
    }

    fc_kernel<<<NG, 128>>>(poolp, fw1, fb1, f1p, 1);
    fc_kernel<<<NG, 128>>>(f1p, fw2, fb2, f2p, 1);
    logits_kernel<<<NG, 32>>>(fw3, fb3, out);
}